// round 15
// baseline (speedup 1.0000x reference)
#include <cuda_runtime.h>

// ContrastiveLoss: z [8192,128] fp32, labels [8192] int32.
// loss = mean over all ordered pairs of: label_eq ? d2 : relu(1 - sqrt(max(d2,0)))^2
//
// pos: closed form per class: sum_{i,j in c} d2 = 2*n_c*S_c - 2*|M_c|^2  (O(N*D))
// neg: only pairs with d2 < 1 contribute. Partial squared distance over the first
//      8 dims is a LOWER bound on d2 -> screen all N^2/2 pairs (ballot batched
//      over 4 j); warp-cooperative exact recheck for rare hits.
// PERSISTENT kernel: 444 blocks (3/SM) pop work items from a queue:
//   items 0..99 = class pos tiles, items 100..675 = screen tiles.
// Last block (ticket) finalizes and resets cross-replay state.

#define NPTS   8192
#define DIM    128
#define NC     100
#define TJ     64
#define NTHR   256
#define IPT    4
#define JB     4                  // j-batch per ballot
#define TI     (NTHR * IPT)       // 1024
#define NBY    (NPTS / TI)        // 8
#define NJX    (NPTS / TJ)        // 128
#define NSCR   576                // productive screen tiles: sum_y (128 - 16y)
#define NITEMS (NSCR + NC)        // 676
#define NPBLK  444                // persistent blocks = 3 per SM x 148
#define THRESH 1.0625f            // screen-out if partial d2 >= THRESH (1 + fp32 slack)
#define FULLM  0xffffffffu

// ---- scratch (no allocations allowed) ----
__device__ double g_pos[NC];       // per-class analytic pos contribution (slot write)
__device__ double g_neg    = 0.0;  // unordered unequal-pair sum; reset by finalizer
__device__ int    g_work   = 0;    // work-queue head; reset by finalizer
__device__ int    g_ticket = 0;    // completion counter; reset by finalizer

__global__ void __launch_bounds__(NTHR, 3)
k_fused(const float* __restrict__ z, const int* __restrict__ lab,
        float* __restrict__ out) {
    __shared__ int    list[NPTS];          // class items: member rows (32KB)
    __shared__ float  sM[NTHR], sQ[NTHR];  // class items: per-(dim,half) partials
    __shared__ float4 sV[TJ][2];           // screen: first 8 dims of j rows
    __shared__ float  sT[TJ];              // screen: partial sq norm of j - THRESH
    __shared__ double redd[NTHR];
    __shared__ int    s_cnt, s_item, s_isLast;

    const int tid   = threadIdx.x;
    const int lane  = tid & 31;
    const int wbase = tid & ~31;

    double wNeg = 0.0;   // per-warp neg accumulator across all popped tiles

    while (true) {
        if (tid == 0) s_item = atomicAdd(&g_work, 1);
        __syncthreads();
        const int item = s_item;
        if (item >= NITEMS) break;

        if (item < NC) {
            // ================= class item: analytic pos term =================
            const int c = item;
            if (tid == 0) s_cnt = 0;
            __syncthreads();
            for (int i = tid; i < NPTS; i += NTHR)
                if (lab[i] == c) list[atomicAdd(&s_cnt, 1)] = i;
            __syncthreads();
            const int cnt = s_cnt;

            // thread owns (dim = tid&127, half = tid>>7); lanes read consecutive
            // dims of the same row -> coalesced 128B lines, L2-resident.
            const int d = tid & 127, half = tid >> 7;
            float m = 0.0f, q = 0.0f;
            for (int k = half; k < cnt; k += 2) {
                float v = __ldg(z + (size_t)list[k] * DIM + d);
                m += v;
                q = fmaf(v, v, q);
            }
            sM[tid] = m; sQ[tid] = q;
            __syncthreads();
            if (tid < 128) {
                float mm = sM[tid] + sM[tid + 128];
                float qq = sQ[tid] + sQ[tid + 128];
                // contribution of this dim: 2*cnt*q_d - 2*m_d^2
                redd[tid] = 2.0 * (double)cnt * (double)qq
                          - 2.0 * (double)mm * (double)mm;
            } else {
                redd[tid] = 0.0;
            }
            __syncthreads();
            for (int s = 128; s > 0; s >>= 1) {
                if (tid < s) redd[tid] += redd[tid + s];
                __syncthreads();
            }
            if (tid == 0) g_pos[c] = redd[0];
        } else {
            // ================= screen item ===================================
            // triangular decode: i-row by has (128 - 16*by) j-tiles
            int rem = item - NC;
            int by = 0;
#pragma unroll
            for (int y = 0; y < NBY; y++) {
                int row = NJX - 16 * y;
                if (rem >= row) { rem -= row; } else { by = y; break; }
            }
            const int I0 = by * TI;
            const int J0 = (16 * by + rem) * TJ;
            const bool needCheck = (J0 < I0 + TI);   // diagonal band

            // stage j tile
            for (int j = tid; j < TJ; j += NTHR) {
                int jg = J0 + j;
                const float4* zr = (const float4*)(z + (size_t)jg * DIM);
                float4 v0 = zr[0], v1 = zr[1];
                float s = v0.x*v0.x + v0.y*v0.y + v0.z*v0.z + v0.w*v0.w
                        + v1.x*v1.x + v1.y*v1.y + v1.z*v1.z + v1.w*v1.w;
                sV[j][0] = v0; sV[j][1] = v1;
                sT[j] = s - THRESH;
            }
            __syncthreads();

            // 4 i-rows per thread, coords pre-scaled by -2 -> pure FMA screen
            float r[IPT][8], ps[IPT];
#pragma unroll
            for (int t = 0; t < IPT; t++) {
                int ig = I0 + tid + t * NTHR;
                const float4* za = (const float4*)(z + (size_t)ig * DIM);
                float4 a0 = za[0], a1 = za[1];
                ps[t] = a0.x*a0.x + a0.y*a0.y + a0.z*a0.z + a0.w*a0.w
                      + a1.x*a1.x + a1.y*a1.y + a1.z*a1.z + a1.w*a1.w;
                r[t][0] = -2.0f*a0.x; r[t][1] = -2.0f*a0.y;
                r[t][2] = -2.0f*a0.z; r[t][3] = -2.0f*a0.w;
                r[t][4] = -2.0f*a1.x; r[t][5] = -2.0f*a1.y;
                r[t][6] = -2.0f*a1.z; r[t][7] = -2.0f*a1.w;
            }

            for (int jb = 0; jb < TJ; jb += JB) {
                float d[JB][IPT];
                float dm[JB];
#pragma unroll
                for (int u = 0; u < JB; u++) {
                    float4 b0 = sV[jb + u][0], b1 = sV[jb + u][1]; // LDS bcast
                    float  stj = sT[jb + u];
#pragma unroll
                    for (int t = 0; t < IPT; t++) {
                        float a = ps[t];
                        a = fmaf(r[t][0], b0.x, a); a = fmaf(r[t][1], b0.y, a);
                        a = fmaf(r[t][2], b0.z, a); a = fmaf(r[t][3], b0.w, a);
                        a = fmaf(r[t][4], b1.x, a); a = fmaf(r[t][5], b1.y, a);
                        a = fmaf(r[t][6], b1.z, a); a = fmaf(r[t][7], b1.w, a);
                        d[u][t] = a;     // = ps_i - 2*dot (partial)
                    }
                    float mn = fminf(fminf(d[u][0], d[u][1]),
                                     fminf(d[u][2], d[u][3]));
                    dm[u] = mn + stj;    // < 0  <=>  partial d2 < THRESH
                }
                float bmn = fminf(fminf(dm[0], dm[1]), fminf(dm[2], dm[3]));

                // one ballot + one (rare) branch per JB j's
                if (__ballot_sync(FULLM, bmn < 0.0f)) {
#pragma unroll
                    for (int u = 0; u < JB; u++) {
                        unsigned bu = __ballot_sync(FULLM, dm[u] < 0.0f);
                        if (bu) {
                            const int   jg  = J0 + jb + u;
                            const int   lj  = lab[jg];
                            const float stj = sT[jb + u];
                            const float4* zjr =
                                (const float4*)(z + (size_t)jg * DIM);
                            float4 bq = zjr[lane];       // lane's quarter of j
                            float sqj = bq.x*bq.x + bq.y*bq.y
                                      + bq.z*bq.z + bq.w*bq.w;
#pragma unroll
                            for (int o = 16; o; o >>= 1)
                                sqj += __shfl_xor_sync(FULLM, sqj, o);
                            while (bu) {
                                int l = __ffs(bu) - 1; bu &= bu - 1;
                                float dd[IPT];
#pragma unroll
                                for (int t = 0; t < IPT; t++)
                                    dd[t] = __shfl_sync(FULLM, d[u][t], l);
                                int ib = I0 + wbase + l;
#pragma unroll
                                for (int t = 0; t < IPT; t++) {
                                    int ig = ib + t * NTHR;
                                    // warp-uniform condition
                                    if (dd[t] + stj < 0.0f &&
                                        (!needCheck || jg > ig) &&
                                        lab[ig] != lj) {
                                        const float4* zir =
                                            (const float4*)(z + (size_t)ig * DIM);
                                        float4 aq = zir[lane];
                                        float part = aq.x*bq.x + aq.y*bq.y
                                                   + aq.z*bq.z + aq.w*bq.w;
                                        float sqi  = aq.x*aq.x + aq.y*aq.y
                                                   + aq.z*aq.z + aq.w*aq.w;
#pragma unroll
                                        for (int o = 16; o; o >>= 1) {
                                            part += __shfl_xor_sync(FULLM, part, o);
                                            sqi  += __shfl_xor_sync(FULLM, sqi, o);
                                        }
                                        if (lane == 0) {
                                            // exact d2, reference formula
                                            float dq = sqi + sqj - 2.0f * part;
                                            if (dq < 1.0f) {
                                                dq = fmaxf(dq, 0.0f);
                                                float mm = 1.0f - sqrtf(dq);
                                                wNeg += (double)(mm * mm);
                                            }
                                        }
                                    }
                                }
                            }
                        }
                    }
                }
            }
        }
        __syncthreads();   // shared arrays quiesce before next item
    }

    if (lane == 0 && wNeg != 0.0) atomicAdd(&g_neg, wNeg);

    // ================= completion ticket + finalize ==========================
    __threadfence();
    __syncthreads();
    if (tid == 0) {
        int old = atomicAdd(&g_ticket, 1);
        s_isLast = (old == NPBLK - 1);
    }
    __syncthreads();
    if (s_isLast) {
        __threadfence();
        redd[tid] = (tid < NC) ? g_pos[tid] : 0.0;
        __syncthreads();
        for (int s = 128; s > 0; s >>= 1) {
            if (tid < s) redd[tid] += redd[tid + s];
            __syncthreads();
        }
        if (tid == 0) {
            double neg = atomicAdd(&g_neg, 0.0);     // atomic read
            double total = redd[0] + 2.0 * neg;
            out[0] = (float)(total / ((double)NPTS * (double)NPTS));
            g_neg = 0.0;       // reset cross-replay state for next graph replay
            g_work = 0;
            g_ticket = 0;
        }
    }
}

extern "C" void kernel_launch(void* const* d_in, const int* in_sizes, int n_in,
                              void* d_out, int out_size) {
    const float* z   = (const float*)d_in[0];
    const int*   lab = (const int*)d_in[1];
    float*       out = (float*)d_out;

    k_fused<<<NPBLK, NTHR>>>(z, lab, out);
}

// round 16
// speedup vs baseline: 1.3436x; 1.3436x over previous
#include <cuda_runtime.h>

// ContrastiveLoss: z [8192,128] fp32, labels [8192] int32.
// loss = mean over all ordered pairs of: label_eq ? d2 : relu(1 - sqrt(max(d2,0)))^2
//
// pos: closed form per class: sum_{i,j in c} d2 = 2*n_c*S_c - 2*|M_c|^2  (O(N*D))
// neg: only pairs with d2 < 1 contribute. Partial squared distance over the first
//      8 dims is a LOWER bound on d2 -> screen all N^2/2 pairs (ONE ballot per
//      8 j; screening values recomputed in the rare slow path).
// SINGLE fused kernel, static grid: blocks 0..99 = class pos, 100..675 = screen.
// Last block (ticket) finalizes and resets cross-replay state.

#define NPTS   8192
#define DIM    128
#define NC     100
#define TJ     64
#define NTHR   256
#define IPT    4
#define JB     8                  // j-batch per ballot
#define TI     (NTHR * IPT)       // 1024
#define NBY    (NPTS / TI)        // 8
#define NJX    (NPTS / TJ)        // 128
#define NSCR   576                // productive screen tiles: sum_y (128 - 16y)
#define NBLK   (NSCR + NC)        // 676
#define THRESH 1.0625f            // screen-out if partial d2 >= THRESH (1 + fp32 slack)
#define FULLM  0xffffffffu

// ---- scratch (no allocations allowed) ----
__device__ double g_pos[NC];       // per-class analytic pos contribution (slot write)
__device__ double g_neg    = 0.0;  // unordered unequal-pair sum; reset by finalizer
__device__ int    g_ticket = 0;    // completion counter; reset by finalizer

__global__ void __launch_bounds__(NTHR, 3)
k_fused(const float* __restrict__ z, const int* __restrict__ lab,
        float* __restrict__ out) {
    __shared__ int    list[NPTS];          // class blocks: member rows (32KB)
    __shared__ float  sM[NTHR], sQ[NTHR];  // class blocks: per-(dim,half) partials
    __shared__ float4 sV[TJ][2];           // screen: first 8 dims of j rows
    __shared__ float  sT[TJ];              // screen: partial sq norm of j - THRESH
    __shared__ double redd[NTHR];
    __shared__ int    s_cnt, s_isLast;

    const int tid   = threadIdx.x;
    const int lane  = tid & 31;
    const int wbase = tid & ~31;

    if ((int)blockIdx.x < NC) {
        // ================= class block: analytic pos term ====================
        const int c = blockIdx.x;
        if (tid == 0) s_cnt = 0;
        __syncthreads();
        for (int i = tid; i < NPTS; i += NTHR)
            if (lab[i] == c) list[atomicAdd(&s_cnt, 1)] = i;
        __syncthreads();
        const int cnt = s_cnt;

        // thread owns (dim = tid&127, half = tid>>7); lanes read consecutive
        // dims of the same row -> coalesced 128B lines, L2-resident.
        const int d = tid & 127, half = tid >> 7;
        float m = 0.0f, q = 0.0f;
        for (int k = half; k < cnt; k += 2) {
            float v = __ldg(z + (size_t)list[k] * DIM + d);
            m += v;
            q = fmaf(v, v, q);
        }
        sM[tid] = m; sQ[tid] = q;
        __syncthreads();
        if (tid < 128) {
            float mm = sM[tid] + sM[tid + 128];
            float qq = sQ[tid] + sQ[tid + 128];
            // contribution of this dim: 2*cnt*q_d - 2*m_d^2
            redd[tid] = 2.0 * (double)cnt * (double)qq
                      - 2.0 * (double)mm * (double)mm;
        } else {
            redd[tid] = 0.0;
        }
        __syncthreads();
        for (int s = 128; s > 0; s >>= 1) {
            if (tid < s) redd[tid] += redd[tid + s];
            __syncthreads();
        }
        if (tid == 0) g_pos[c] = redd[0];
    } else {
        // ================= screen block ======================================
        // 1D triangular decode: i-row by has (128 - 16*by) j-tiles
        int rem = (int)blockIdx.x - NC;
        int by = 0;
#pragma unroll
        for (int y = 0; y < NBY; y++) {
            int row = NJX - 16 * y;
            if (rem >= row) { rem -= row; } else { by = y; break; }
        }
        const int I0 = by * TI;
        const int J0 = (16 * by + rem) * TJ;
        const bool needCheck = (J0 < I0 + TI);   // diagonal band

        // stage j tile
        for (int j = tid; j < TJ; j += NTHR) {
            int jg = J0 + j;
            const float4* zr = (const float4*)(z + (size_t)jg * DIM);
            float4 v0 = zr[0], v1 = zr[1];
            float s = v0.x*v0.x + v0.y*v0.y + v0.z*v0.z + v0.w*v0.w
                    + v1.x*v1.x + v1.y*v1.y + v1.z*v1.z + v1.w*v1.w;
            sV[j][0] = v0; sV[j][1] = v1;
            sT[j] = s - THRESH;
        }
        __syncthreads();

        // 4 i-rows per thread, coords pre-scaled by -2 -> pure FMA screen
        float r[IPT][8], ps[IPT];
#pragma unroll
        for (int t = 0; t < IPT; t++) {
            int ig = I0 + tid + t * NTHR;
            const float4* za = (const float4*)(z + (size_t)ig * DIM);
            float4 a0 = za[0], a1 = za[1];
            ps[t] = a0.x*a0.x + a0.y*a0.y + a0.z*a0.z + a0.w*a0.w
                  + a1.x*a1.x + a1.y*a1.y + a1.z*a1.z + a1.w*a1.w;
            r[t][0] = -2.0f*a0.x; r[t][1] = -2.0f*a0.y;
            r[t][2] = -2.0f*a0.z; r[t][3] = -2.0f*a0.w;
            r[t][4] = -2.0f*a1.x; r[t][5] = -2.0f*a1.y;
            r[t][6] = -2.0f*a1.z; r[t][7] = -2.0f*a1.w;
        }

        double wNeg = 0.0;   // per-warp accumulator (lane 0 writes)

        for (int jb = 0; jb < TJ; jb += JB) {
            // fast path: compute dm[u] only; screening dots are DISCARDED and
            // recomputed in the (rare) slow path -> fewer live regs, 1 ballot/8j
            float dm[JB];
#pragma unroll
            for (int u = 0; u < JB; u++) {
                float4 b0 = sV[jb + u][0], b1 = sV[jb + u][1];   // LDS broadcast
                float  stj = sT[jb + u];
                float mn;
#pragma unroll
                for (int t = 0; t < IPT; t++) {
                    float a = ps[t];
                    a = fmaf(r[t][0], b0.x, a); a = fmaf(r[t][1], b0.y, a);
                    a = fmaf(r[t][2], b0.z, a); a = fmaf(r[t][3], b0.w, a);
                    a = fmaf(r[t][4], b1.x, a); a = fmaf(r[t][5], b1.y, a);
                    a = fmaf(r[t][6], b1.z, a); a = fmaf(r[t][7], b1.w, a);
                    mn = (t == 0) ? a : fminf(mn, a);
                }
                dm[u] = mn + stj;    // < 0  <=>  some partial d2 < THRESH
            }
            float bmn = dm[0];
#pragma unroll
            for (int u = 1; u < JB; u++) bmn = fminf(bmn, dm[u]);

            // one ballot + one (rare) branch per JB j's
            if (__ballot_sync(FULLM, bmn < 0.0f)) {
#pragma unroll
                for (int u = 0; u < JB; u++) {
                    unsigned bu = __ballot_sync(FULLM, dm[u] < 0.0f);
                    if (bu) {
                        // recompute this batch-member's screening dots
                        float4 b0 = sV[jb + u][0], b1 = sV[jb + u][1];
                        const float stj = sT[jb + u];
                        float dre[IPT];
#pragma unroll
                        for (int t = 0; t < IPT; t++) {
                            float a = ps[t];
                            a = fmaf(r[t][0], b0.x, a); a = fmaf(r[t][1], b0.y, a);
                            a = fmaf(r[t][2], b0.z, a); a = fmaf(r[t][3], b0.w, a);
                            a = fmaf(r[t][4], b1.x, a); a = fmaf(r[t][5], b1.y, a);
                            a = fmaf(r[t][6], b1.z, a); a = fmaf(r[t][7], b1.w, a);
                            dre[t] = a;
                        }
                        const int jg = J0 + jb + u;
                        const int lj = lab[jg];
                        const float4* zjr = (const float4*)(z + (size_t)jg * DIM);
                        float4 bq = zjr[lane];           // lane's quarter of row j
                        float sqj = bq.x*bq.x + bq.y*bq.y + bq.z*bq.z + bq.w*bq.w;
#pragma unroll
                        for (int o = 16; o; o >>= 1)
                            sqj += __shfl_xor_sync(FULLM, sqj, o);
                        while (bu) {
                            int l = __ffs(bu) - 1; bu &= bu - 1;
                            float dd[IPT];
#pragma unroll
                            for (int t = 0; t < IPT; t++)
                                dd[t] = __shfl_sync(FULLM, dre[t], l);
                            int ib = I0 + wbase + l;
#pragma unroll
                            for (int t = 0; t < IPT; t++) {
                                int ig = ib + t * NTHR;
                                // warp-uniform condition (all operands uniform)
                                if (dd[t] + stj < 0.0f &&
                                    (!needCheck || jg > ig) && lab[ig] != lj) {
                                    const float4* zir =
                                        (const float4*)(z + (size_t)ig * DIM);
                                    float4 aq = zir[lane];
                                    float part = aq.x*bq.x + aq.y*bq.y
                                               + aq.z*bq.z + aq.w*bq.w;
                                    float sqi  = aq.x*aq.x + aq.y*aq.y
                                               + aq.z*aq.z + aq.w*aq.w;
#pragma unroll
                                    for (int o = 16; o; o >>= 1) {
                                        part += __shfl_xor_sync(FULLM, part, o);
                                        sqi  += __shfl_xor_sync(FULLM, sqi, o);
                                    }
                                    if (lane == 0) {
                                        // exact d2, same formula as the reference
                                        float dq = sqi + sqj - 2.0f * part;
                                        if (dq < 1.0f) {
                                            dq = fmaxf(dq, 0.0f);
                                            float mm = 1.0f - sqrtf(dq);
                                            wNeg += (double)(mm * mm); // x2 below
                                        }
                                    }
                                }
                            }
                        }
                    }
                }
            }
        }
        if (lane == 0 && wNeg != 0.0) atomicAdd(&g_neg, wNeg);
    }

    // ================= completion ticket + finalize ==========================
    __threadfence();
    __syncthreads();
    if (tid == 0) {
        int old = atomicAdd(&g_ticket, 1);
        s_isLast = (old == NBLK - 1);
    }
    __syncthreads();
    if (s_isLast) {
        __threadfence();
        redd[tid] = (tid < NC) ? g_pos[tid] : 0.0;
        __syncthreads();
        for (int s = 128; s > 0; s >>= 1) {
            if (tid < s) redd[tid] += redd[tid + s];
            __syncthreads();
        }
        if (tid == 0) {
            double neg = atomicAdd(&g_neg, 0.0);     // atomic read
            double total = redd[0] + 2.0 * neg;
            out[0] = (float)(total / ((double)NPTS * (double)NPTS));
            g_neg = 0.0;       // reset cross-replay state for next graph replay
            g_ticket = 0;
        }
    }
}

extern "C" void kernel_launch(void* const* d_in, const int* in_sizes, int n_in,
                              void* d_out, int out_size) {
    const float* z   = (const float*)d_in[0];
    const int*   lab = (const int*)d_in[1];
    float*       out = (float*)d_out;

    k_fused<<<NBLK, NTHR>>>(z, lab, out);
}

// round 17
// speedup vs baseline: 2.4803x; 1.8460x over previous
#include <cuda_runtime.h>
#include <cstdint>

// ContrastiveLoss: z [8192,128] fp32, labels [8192] int32.
// loss = mean over all ordered pairs of: label_eq ? d2 : relu(1 - sqrt(max(d2,0)))^2
//
// pos: closed form per class: sum_{i,j in c} d2 = 2*n_c*S_c - 2*|M_c|^2  (O(N*D))
// neg: only pairs with d2 < 1 contribute. Partial squared distance over the first
//      8 dims is a LOWER bound on d2. Screen all N^2/2 pairs with tf32
//      mma.sync.m16n8k8 (128 pair-dots per HMMA); THRESH=1.5 absorbs tf32
//      rounding, exact fp32 128-dim warp recheck for rare candidates.
// Blocks 0..99 = class pos, 100..1155 = screen tiles. Ticket finalize.

#define NPTS   8192
#define DIM    128
#define NC     100
#define TJ     128
#define NTHR   256
#define TI     256                // 8 warps x 32 i-rows
#define NBY    (NPTS / TI)        // 32
#define NJX    (NPTS / TJ)        // 64
#define NSCR   1056               // sum_{by} (64 - 2*by)
#define NBLK   (NSCR + NC)        // 1156
#define THRESH 1.5f               // 1.0 margin + fp32 slack + tf32 dot error bound
#define FULLM  0xffffffffu

// ---- scratch (no allocations allowed) ----
__device__ double g_pos[NC];       // per-class analytic pos contribution
__device__ double g_neg    = 0.0;  // unordered unequal-pair sum; reset by finalizer
__device__ int    g_ticket = 0;    // completion counter; reset by finalizer

__device__ __forceinline__ uint32_t f2tf32(float f) {
    uint32_t r;
    asm("cvt.rna.tf32.f32 %0, %1;" : "=r"(r) : "f"(f));
    return r;
}
// D = A(16x8,row) * B(8x8,col) + 0 ; tf32 inputs, f32 accum
__device__ __forceinline__ void mma8(float* d, const uint32_t* a, const uint32_t* b) {
    asm("mma.sync.aligned.m16n8k8.row.col.f32.tf32.tf32.f32 "
        "{%0,%1,%2,%3}, {%4,%5,%6,%7}, {%8,%9}, {%10,%11,%12,%13};"
        : "=f"(d[0]), "=f"(d[1]), "=f"(d[2]), "=f"(d[3])
        : "r"(a[0]), "r"(a[1]), "r"(a[2]), "r"(a[3]),
          "r"(b[0]), "r"(b[1]),
          "f"(0.0f), "f"(0.0f), "f"(0.0f), "f"(0.0f));
}

__global__ void __launch_bounds__(NTHR, 4)
k_fused(const float* __restrict__ z, const int* __restrict__ lab,
        float* __restrict__ out) {
    __shared__ int      list[NPTS];          // class blocks: member rows (32KB)
    __shared__ float    sM[NTHR], sQ[NTHR];  // class blocks: per-(dim,half) partials
    __shared__ uint32_t sB[TJ * 8];          // screen: tf32(z_j[0..7]) per j
    __shared__ float    sT[TJ];              // screen: ps_j - THRESH
    __shared__ double   redd[NTHR];
    __shared__ int      s_cnt, s_isLast;

    const int tid  = threadIdx.x;
    const int lane = tid & 31;

    if ((int)blockIdx.x < NC) {
        // ================= class block: analytic pos term ====================
        const int c = blockIdx.x;
        if (tid == 0) s_cnt = 0;
        __syncthreads();
        for (int i = tid; i < NPTS; i += NTHR)
            if (lab[i] == c) list[atomicAdd(&s_cnt, 1)] = i;
        __syncthreads();
        const int cnt = s_cnt;

        // thread owns (dim = tid&127, half = tid>>7); coalesced 128B row reads
        const int d = tid & 127, half = tid >> 7;
        float m = 0.0f, q = 0.0f;
        for (int k = half; k < cnt; k += 2) {
            float v = __ldg(z + (size_t)list[k] * DIM + d);
            m += v;
            q = fmaf(v, v, q);
        }
        sM[tid] = m; sQ[tid] = q;
        __syncthreads();
        if (tid < 128) {
            float mm = sM[tid] + sM[tid + 128];
            float qq = sQ[tid] + sQ[tid + 128];
            redd[tid] = 2.0 * (double)cnt * (double)qq
                      - 2.0 * (double)mm * (double)mm;
        } else {
            redd[tid] = 0.0;
        }
        __syncthreads();
        for (int s = 128; s > 0; s >>= 1) {
            if (tid < s) redd[tid] += redd[tid + s];
            __syncthreads();
        }
        if (tid == 0) g_pos[c] = redd[0];
    } else {
        // ================= screen block (tf32 MMA) ===========================
        // triangular decode: i-row band by has (64 - 2*by) j-tiles, jx = 2by+rem
        int rem = (int)blockIdx.x - NC;
        int by = 0;
#pragma unroll
        for (int y = 0; y < NBY; y++) {
            int row = NJX - 2 * y;
            if (rem >= row) { rem -= row; } else { by = y; break; }
        }
        const int I0 = by * TI;
        const int J0 = (2 * by + rem) * TJ;
        const bool needCheck = (rem <= 1);       // J-range overlaps I-range

        // stage j tile: tf32-converted first 8 dims + (ps_j - THRESH)
        for (int j = tid; j < TJ; j += NTHR) {
            int jg = J0 + j;
            const float4* zr = (const float4*)(z + (size_t)jg * DIM);
            float4 v0 = zr[0], v1 = zr[1];
            float s = v0.x*v0.x + v0.y*v0.y + v0.z*v0.z + v0.w*v0.w
                    + v1.x*v1.x + v1.y*v1.y + v1.z*v1.z + v1.w*v1.w;
            sT[j] = s - THRESH;
            uint32_t* b = &sB[j * 8];
            b[0] = f2tf32(v0.x); b[1] = f2tf32(v0.y);
            b[2] = f2tf32(v0.z); b[3] = f2tf32(v0.w);
            b[4] = f2tf32(v1.x); b[5] = f2tf32(v1.y);
            b[6] = f2tf32(v1.z); b[7] = f2tf32(v1.w);
        }
        __syncthreads();

        const int w  = tid >> 5;
        const int g  = lane >> 2;        // groupID (0..7)
        const int tg = lane & 3;         // threadID_in_group (0..3)
        const int rowBase = I0 + w * 32; // warp owns 32 i-rows

        // A fragments: 2 x m16k8 of (-2 * z_i) in tf32; plus 8-dim partial norms
        uint32_t A[2][4];
        float    psi[2][2];              // [frag][row g | row g+8]
#pragma unroll
        for (int f = 0; f < 2; f++) {
            int rg = rowBase + f * 16 + g;
            const float* zr  = z + (size_t)rg * DIM;
            const float* zr8 = z + (size_t)(rg + 8) * DIM;
            float a0 = zr[tg],  a2 = zr[tg + 4];    // row g,  cols tg, tg+4
            float a1 = zr8[tg], a3 = zr8[tg + 4];   // row g+8
            float slo = a0 * a0 + a2 * a2;
            float shi = a1 * a1 + a3 * a3;
            slo += __shfl_xor_sync(FULLM, slo, 1);
            slo += __shfl_xor_sync(FULLM, slo, 2);
            shi += __shfl_xor_sync(FULLM, shi, 1);
            shi += __shfl_xor_sync(FULLM, shi, 2);
            psi[f][0] = slo; psi[f][1] = shi;
            A[f][0] = f2tf32(-2.0f * a0);
            A[f][1] = f2tf32(-2.0f * a1);
            A[f][2] = f2tf32(-2.0f * a2);
            A[f][3] = f2tf32(-2.0f * a3);
        }

        double wNeg = 0.0;   // per-warp accumulator (lane 0 writes)

        for (int jt4 = 0; jt4 < TJ / 8; jt4 += 4) {
            float gmin = 1e30f;
#pragma unroll
            for (int u = 0; u < 4; u++) {
                int jt = jt4 + u;
                // B frag: b0 = z[J0+jt*8+g][tg], b1 = [tg+4]
                uint32_t Bf[2] = { sB[(jt * 8 + g) * 8 + tg],
                                   sB[(jt * 8 + g) * 8 + tg + 4] };
                float2 uu = *(const float2*)&sT[jt * 8 + 2 * tg];  // cols 2tg,2tg+1
                float d0[4], d1[4];
                mma8(d0, A[0], Bf);
                mma8(d1, A[1], Bf);
                // pd2 - THRESH = acc + ps_i + (ps_j - THRESH)
                float m0 = fminf(fminf(d0[0] + (psi[0][0] + uu.x),
                                       d0[1] + (psi[0][0] + uu.y)),
                                 fminf(d0[2] + (psi[0][1] + uu.x),
                                       d0[3] + (psi[0][1] + uu.y)));
                float m1 = fminf(fminf(d1[0] + (psi[1][0] + uu.x),
                                       d1[1] + (psi[1][0] + uu.y)),
                                 fminf(d1[2] + (psi[1][1] + uu.x),
                                       d1[3] + (psi[1][1] + uu.y)));
                gmin = fminf(gmin, fminf(m0, m1));
            }

            if (__ballot_sync(FULLM, gmin < 0.0f)) {
                // slow path: recompute per tile, find exact candidates
                for (int u = 0; u < 4; u++) {
                    int jt = jt4 + u;
                    uint32_t Bf[2] = { sB[(jt * 8 + g) * 8 + tg],
                                       sB[(jt * 8 + g) * 8 + tg + 4] };
                    float2 uu = *(const float2*)&sT[jt * 8 + 2 * tg];
                    float d0[4], d1[4];
                    mma8(d0, A[0], Bf);
                    mma8(d1, A[1], Bf);
                    int cmask = 0;
                    // bit q = f*4 + r; r: 0=(g,2tg) 1=(g,2tg+1) 2=(g+8,2tg) 3=(g+8,2tg+1)
                    if (d0[0] + psi[0][0] + uu.x < 0.0f) cmask |= 1 << 0;
                    if (d0[1] + psi[0][0] + uu.y < 0.0f) cmask |= 1 << 1;
                    if (d0[2] + psi[0][1] + uu.x < 0.0f) cmask |= 1 << 2;
                    if (d0[3] + psi[0][1] + uu.y < 0.0f) cmask |= 1 << 3;
                    if (d1[0] + psi[1][0] + uu.x < 0.0f) cmask |= 1 << 4;
                    if (d1[1] + psi[1][0] + uu.y < 0.0f) cmask |= 1 << 5;
                    if (d1[2] + psi[1][1] + uu.x < 0.0f) cmask |= 1 << 6;
                    if (d1[3] + psi[1][1] + uu.y < 0.0f) cmask |= 1 << 7;

                    unsigned hit = __ballot_sync(FULLM, cmask != 0);
                    while (hit) {
                        int l = __ffs(hit) - 1; hit &= hit - 1;
                        int cm  = __shfl_sync(FULLM, cmask, l);
                        int lg  = l >> 2, ltg = l & 3;
                        while (cm) {
                            int q = __ffs(cm) - 1; cm &= cm - 1;
                            int f = q >> 2, r = q & 3;
                            int ig = rowBase + f * 16 + lg + ((r >= 2) ? 8 : 0);
                            int jg = J0 + jt * 8 + 2 * ltg + (r & 1);
                            // warp-uniform condition (ig, jg uniform)
                            if ((!needCheck || jg > ig) && lab[ig] != lab[jg]) {
                                // exact fp32 d2, same formula as the reference
                                const float4* zir = (const float4*)(z + (size_t)ig * DIM);
                                const float4* zjr = (const float4*)(z + (size_t)jg * DIM);
                                float4 aq = zir[lane], bq = zjr[lane];
                                float part = aq.x*bq.x + aq.y*bq.y + aq.z*bq.z + aq.w*bq.w;
                                float sqi  = aq.x*aq.x + aq.y*aq.y + aq.z*aq.z + aq.w*aq.w;
                                float sqj  = bq.x*bq.x + bq.y*bq.y + bq.z*bq.z + bq.w*bq.w;
#pragma unroll
                                for (int o = 16; o; o >>= 1) {
                                    part += __shfl_xor_sync(FULLM, part, o);
                                    sqi  += __shfl_xor_sync(FULLM, sqi, o);
                                    sqj  += __shfl_xor_sync(FULLM, sqj, o);
                                }
                                if (lane == 0) {
                                    float dq = sqi + sqj - 2.0f * part;
                                    if (dq < 1.0f) {
                                        dq = fmaxf(dq, 0.0f);
                                        float mm = 1.0f - sqrtf(dq);
                                        wNeg += (double)(mm * mm);   // x2 below
                                    }
                                }
                            }
                        }
                    }
                }
            }
        }
        if (lane == 0 && wNeg != 0.0) atomicAdd(&g_neg, wNeg);
    }

    // ================= completion ticket + finalize ==========================
    __threadfence();
    __syncthreads();
    if (tid == 0) {
        int old = atomicAdd(&g_ticket, 1);
        s_isLast = (old == NBLK - 1);
    }
    __syncthreads();
    if (s_isLast) {
        __threadfence();
        redd[tid] = (tid < NC) ? g_pos[tid] : 0.0;
        __syncthreads();
        for (int s = 128; s > 0; s >>= 1) {
            if (tid < s) redd[tid] += redd[tid + s];
            __syncthreads();
        }
        if (tid == 0) {
            double neg = atomicAdd(&g_neg, 0.0);     // atomic read
            double total = redd[0] + 2.0 * neg;
            out[0] = (float)(total / ((double)NPTS * (double)NPTS));
            g_neg = 0.0;       // reset cross-replay state for next graph replay
            g_ticket = 0;
        }
    }
}

extern "C" void kernel_launch(void* const* d_in, const int* in_sizes, int n_in,
                              void* d_out, int out_size) {
    const float* z   = (const float*)d_in[0];
    const int*   lab = (const int*)d_in[1];
    float*       out = (float*)d_out;

    k_fused<<<NBLK, NTHR>>>(z, lab, out);
}